// round 2
// baseline (speedup 1.0000x reference)
#include <cuda_runtime.h>
#include <cuda_bf16.h>

// Problem: pendulum RK4 trajectory.
// Inputs (metadata order): mini_batch (N*2, unused), t (T=100), z0 (N*2), params (N*1)
// Output: float out[N][T][2]  (theta, omega per step; step 0 = z0)
//
// Per-particle ODE: theta' = omega; omega' = -(G/L) sin(theta); L' = 0.
// RK4 "alt" form from the reference:
//   k1 = f(y)
//   k2 = f(y + dt*k1/3)
//   k3 = f(y + dt*(k2 - k1/3))
//   k4 = f(y + dt*(k1 - k2 + k3))
//   y += dt*(k1 + 3*(k2+k3) + k4)/8

#define PEND_N 200000
#define PEND_T 100
#define PEND_G 10.0f

__global__ __launch_bounds__(256) void pendulum_rk4_kernel(
    const float* __restrict__ t,
    const float* __restrict__ z0,
    const float* __restrict__ params,
    float* __restrict__ out,
    int n)
{
    // Stage dts in shared memory. All threads of the block participate
    // (before any early exit) so __syncthreads is uniform.
    __shared__ float sdt[PEND_T - 1];
    for (int j = threadIdx.x; j < PEND_T - 1; j += blockDim.x)
        sdt[j] = t[j + 1] - t[j];
    __syncthreads();

    const float third = 1.0f / 3.0f;

    for (int i = blockIdx.x * blockDim.x + threadIdx.x; i < n;
         i += gridDim.x * blockDim.x) {

        const float2 z = reinterpret_cast<const float2*>(z0)[i];
        float theta = z.x;
        float omega = z.y;
        const float L = params[i];
        const float coef = -(PEND_G / L);   // omega' = coef * sin(theta)

        float2* o = reinterpret_cast<float2*>(out) + (size_t)i * PEND_T;
        o[0] = make_float2(theta, omega);

        #pragma unroll 1
        for (int s = 0; s < PEND_T - 1; s++) {
            const float dt = sdt[s];

            // k1
            const float k1t = omega;
            const float k1w = coef * __sinf(theta);
            // k2 at y + dt*k1/3
            const float y2t = theta + dt * (k1t * third);
            const float y2w = omega + dt * (k1w * third);
            const float k2t = y2w;
            const float k2w = coef * __sinf(y2t);
            // k3 at y + dt*(k2 - k1/3)
            const float y3t = theta + dt * (k2t - k1t * third);
            const float y3w = omega + dt * (k2w - k1w * third);
            const float k3t = y3w;
            const float k3w = coef * __sinf(y3t);
            // k4 at y + dt*(k1 - k2 + k3)
            const float y4t = theta + dt * (k1t - k2t + k3t);
            const float y4w = omega + dt * (k1w - k2w + k3w);
            const float k4t = y4w;
            const float k4w = coef * __sinf(y4t);
            // combine
            theta += dt * (k1t + 3.0f * (k2t + k3t) + k4t) * 0.125f;
            omega += dt * (k1w + 3.0f * (k2w + k3w) + k4w) * 0.125f;

            o[s + 1] = make_float2(theta, omega);
        }
    }
}

extern "C" void kernel_launch(void* const* d_in, const int* in_sizes, int n_in,
                              void* d_out, int out_size)
{
    // d_in[0] = mini_batch (unused), d_in[1] = t, d_in[2] = z0, d_in[3] = params
    const float* t      = (const float*)d_in[1];
    const float* z0     = (const float*)d_in[2];
    const float* params = (const float*)d_in[3];
    float* out          = (float*)d_out;

    const int n = in_sizes[3];          // params has N elements
    const int threads = 256;
    const int blocks  = (n + threads - 1) / threads;
    pendulum_rk4_kernel<<<blocks, threads>>>(t, z0, params, out, n);
}

// round 4
// speedup vs baseline: 6.3402x; 6.3402x over previous
#include <cuda_runtime.h>
#include <cuda_bf16.h>

// Pendulum RK4 trajectory, N=200000 particles, T=100 time slots.
// out[N][T][2] float32. Slot 0 = initial state, slot s = state after s steps.
//
// R2 lesson: scalar float2 stores at 800B lane stride = 32 L1tex wavefronts
// per warp-store -> LSU backpressure stalls the whole SM (issue was 9.8%).
// R3/R4: buffer 16 slots/particle in smem, flush via warp transpose with
// coalesced float4 stores. In each flush iteration, lanes 8k..8k+7 write one
// particle's 16-slot chunk = one full 128B line -> 4 full lines per warp-store.

#define PEND_N 200000
#define PEND_T 100
#define PEND_G 10.0f
#define TC      16          // full chunk: slots per flush
#define ROWF2   18          // padded row length in float2 (144B, 16B-aligned)
#define NWARPS  8           // 256 threads / 32

__global__ __launch_bounds__(256) void pendulum_rk4_kernel(
    const float* __restrict__ t,
    const float* __restrict__ z0,
    const float* __restrict__ params,
    float* __restrict__ out,
    int n)
{
    __shared__ float sdt[PEND_T - 1];
    __shared__ __align__(16) float2 buf[NWARPS][32][ROWF2];

    // Stage dts (all threads participate before any early exit).
    for (int j = threadIdx.x; j < PEND_T - 1; j += blockDim.x)
        sdt[j] = t[j + 1] - t[j];
    __syncthreads();

    const int warp = threadIdx.x >> 5;
    const int lane = threadIdx.x & 31;
    const int warpbase = blockIdx.x * blockDim.x + warp * 32;   // first particle of warp
    if (warpbase >= n) return;            // n is a multiple of 32: whole warps only

    float2 (* __restrict__ mybuf)[ROWF2] = buf[warp];

    const int i = warpbase + lane;        // this thread's particle
    const float2 z = reinterpret_cast<const float2*>(z0)[i];
    float theta = z.x;
    float omega = z.y;
    const float coef = -(PEND_G / params[i]);     // omega' = coef * sin(theta)
    const float third = 1.0f / 3.0f;

    float4* __restrict__ out4 = reinterpret_cast<float4*>(out);
    const size_t rowbase = (size_t)warpbase * (PEND_T / 2);     // float4 per row = 50

    int base = 0;                                  // global slot index of chunk start
    #pragma unroll 1
    for (int c = 0; c < 7; c++) {
        const int cnt = (c < 6) ? TC : (PEND_T - 6 * TC);       // 16 x6, then 4

        // ---- compute cnt slots into smem ----
        #pragma unroll 1
        for (int k = 0; k < cnt; k++) {
            const int g = base + k;                // uniform across warp
            if (g > 0) {
                const float dt = sdt[g - 1];
                // k1
                const float k1t = omega;
                const float k1w = coef * __sinf(theta);
                // k2 at y + dt*k1/3
                const float y2t = theta + dt * (k1t * third);
                const float y2w = omega + dt * (k1w * third);
                const float k2t = y2w;
                const float k2w = coef * __sinf(y2t);
                // k3 at y + dt*(k2 - k1/3)
                const float y3t = theta + dt * (k2t - k1t * third);
                const float y3w = omega + dt * (k2w - k1w * third);
                const float k3t = y3w;
                const float k3w = coef * __sinf(y3t);
                // k4 at y + dt*(k1 - k2 + k3)
                const float y4t = theta + dt * (k1t - k2t + k3t);
                const float y4w = omega + dt * (k1w - k2w + k3w);
                const float k4t = y4w;
                const float k4w = coef * __sinf(y4t);
                // combine
                theta += dt * (k1t + 3.0f * (k2t + k3t) + k4t) * 0.125f;
                omega += dt * (k1w + 3.0f * (k2w + k3w) + k4w) * 0.125f;
            }
            mybuf[lane][k] = make_float2(theta, omega);
        }
        __syncwarp();

        // ---- flush: warp transpose, coalesced float4 stores ----
        const int f4pp = cnt >> 1;                 // float4 per particle (8 or 2)
        #pragma unroll
        for (int j = 0; j < TC / 2; j++) {
            if (j >= f4pp) break;
            const int idx = j * 32 + lane;         // flat float4 index in tile
            const int p   = idx / f4pp;            // particle within warp
            const int s4  = idx - p * f4pp;        // float4 slot within particle
            const float4 v = *reinterpret_cast<const float4*>(&mybuf[p][s4 * 2]);
            out4[rowbase + (size_t)p * (PEND_T / 2) + (base >> 1) + s4] = v;
        }
        __syncwarp();

        base += cnt;
    }
}

extern "C" void kernel_launch(void* const* d_in, const int* in_sizes, int n_in,
                              void* d_out, int out_size)
{
    (void)n_in; (void)out_size;
    // d_in[0] = mini_batch (unused), d_in[1] = t, d_in[2] = z0, d_in[3] = params
    const float* t      = (const float*)d_in[1];
    const float* z0     = (const float*)d_in[2];
    const float* params = (const float*)d_in[3];
    float* out          = (float*)d_out;

    const int n = in_sizes[3];          // params has N elements
    const int threads = 256;
    const int blocks  = (n + threads - 1) / threads;
    pendulum_rk4_kernel<<<blocks, threads>>>(t, z0, params, out, n);
}